// round 3
// baseline (speedup 1.0000x reference)
#include <cuda_runtime.h>
#include <cstdint>
#include <math.h>

// ---------------- problem constants ----------------
#define D_MODEL 64
#define HID     128
#define NRULES  4
#define K1      192              // 3*D_MODEL
#define BB      32
#define TT      8192
#define NTOK    (BB*TT)          // 262144
#define TILE    128              // tokens per block
#define NBLK    (NTOK/TILE)      // 2048
#define NTHR    512
#define LN_EPS  1e-5f

// ---------------- smem layout (floats) ----------------
#define OFF_X   0
#define SZ_X    (130*64)         // halo tile: tokens t0-1 .. t0+128
#define OFF_W1  (OFF_X + SZ_X)
#define SZ_W1   (K1*HID)         // 24576
#define OFF_W2  (OFF_W1 + SZ_W1)
#define SZ_W2   (HID*D_MODEL)    // 8192
#define HPITCH  132
#define OFF_H   (OFF_W2 + SZ_W2)
#define SZ_H    (128*HPITCH)     // 16896
#define SMEM_FLOATS (OFF_H + SZ_H)         // 57984
#define SMEM_BYTES  (SMEM_FLOATS*4)        // 231936 B

// ---------------- device state ----------------
__device__ float g_rw[4];
__device__ float g_alpha;
__device__ int   g_nev;
__device__ float g_buf0[(size_t)NTOK*D_MODEL];
__device__ float g_buf1[(size_t)NTOK*D_MODEL];

// ---------------- packed f32x2 helpers ----------------
typedef unsigned long long ull;

__device__ __forceinline__ ull fma2(ull a, ull b, ull c){
    ull d; asm("fma.rn.f32x2 %0, %1, %2, %3;" : "=l"(d) : "l"(a), "l"(b), "l"(c)); return d;
}
__device__ __forceinline__ ull dup2(float a){
    ull d; asm("mov.b64 %0, {%1, %2};" : "=l"(d) : "f"(a), "f"(a)); return d;
}
__device__ __forceinline__ float2 unp2(ull v){
    float2 r; asm("mov.b64 {%0, %1}, %2;" : "=f"(r.x), "=f"(r.y) : "l"(v)); return r;
}

__device__ __forceinline__ float gelu_exact(float x){
    return 0.5f * x * (1.0f + erff(x * 0.7071067811865475f));
}

// ---------------- control kernel ----------------
__global__ void control_kernel(
    const float* __restrict__ c,
    const float* __restrict__ p_sw1, const float* __restrict__ p_sb1,
    const float* __restrict__ p_sw2, const float* __restrict__ p_sb2,
    const float* __restrict__ p_tw1, const float* __restrict__ p_tb1,
    const float* __restrict__ p_tw2, const float* __restrict__ p_tb2,
    const float* __restrict__ p_rw1, const float* __restrict__ p_rb1,
    const float* __restrict__ p_rw2, const float* __restrict__ p_rb2)
{
    __shared__ float cs[128];
    __shared__ float h1[64];
    __shared__ float h2[32];
    __shared__ float h3[32];
    int t = threadIdx.x;
    if (t < 128) cs[t] = c[t];
    __syncthreads();

    if (t < 64){
        float a = p_sb1[t];
        for (int k = 0; k < 128; k++) a += cs[k] * p_sw1[k*64 + t];
        h1[t] = gelu_exact(a);
    } else if (t < 96){
        int i = t - 64;
        float a = p_tb1[i];
        for (int k = 0; k < 128; k++) a += cs[k] * p_tw1[k*32 + i];
        h2[i] = gelu_exact(a);
    } else {
        int i = t - 96;
        float a = p_rb1[i];
        for (int k = 0; k < 128; k++) a += cs[k] * p_rw1[k*32 + i];
        h3[i] = gelu_exact(a);
    }
    __syncthreads();

    if (t == 0){
        float l[4]; float mx = -1e30f;
        for (int r = 0; r < 4; r++){
            float a = p_sb2[r];
            for (int i = 0; i < 64; i++) a += h1[i] * p_sw2[i*4 + r];
            l[r] = a; mx = fmaxf(mx, a);
        }
        float s = 0.0f;
        for (int r = 0; r < 4; r++){ l[r] = expf(l[r] - mx); s += l[r]; }
        for (int r = 0; r < 4; r++) g_rw[r] = l[r] / s;
    }
    if (t == 1){
        float l[7]; float mx = -1e30f;
        for (int jj = 0; jj < 7; jj++){
            float a = p_tb2[jj];
            for (int i = 0; i < 32; i++) a += h2[i] * p_tw2[i*7 + jj];
            l[jj] = a; mx = fmaxf(mx, a);
        }
        float s = 0.0f;
        for (int jj = 0; jj < 7; jj++){ l[jj] = expf(l[jj] - mx); s += l[jj]; }
        const float steps[7] = {2.0f,3.0f,4.0f,5.0f,6.0f,7.0f,8.0f};
        float nf = 0.0f;
        for (int jj = 0; jj < 7; jj++) nf += (l[jj] / s) * steps[jj];
        int n = (int)(nf + 0.5f);
        if (n < 2) n = 2;
        if (n > 8) n = 8;
        g_nev = n;
    }
    if (t == 2){
        float v = p_rb2[0];
        for (int i = 0; i < 32; i++) v += h3[i] * p_rw2[i];
        g_alpha = 0.1f + 0.8f / (1.0f + expf(-v));
    }
}

// ---------------- evolve step ----------------
__global__ void __launch_bounds__(NTHR, 1)
step_kernel(const float* __restrict__ cells_in,
            const float* __restrict__ rw1, const float* __restrict__ rb1,
            const float* __restrict__ rw2, const float* __restrict__ rb2,
            int j)
{
    if (j >= g_nev) return;

    extern __shared__ float sm[];
    float* x_s  = sm + OFF_X;
    float* w1s  = sm + OFF_W1;
    float* w2s  = sm + OFF_W2;
    float* h_s  = sm + OFF_H;
    __shared__ float rw_s[4];
    __shared__ float alpha_s;

    const float* src = (j == 0) ? cells_in : ((j & 1) ? g_buf0 : g_buf1);
    float*       dst = (j & 1) ? g_buf1 : g_buf0;

    const int tid  = threadIdx.x;
    const int brow = blockIdx.x >> 6;
    const int t0   = (blockIdx.x & 63) << 7;
    const float* rowbase = src + (size_t)brow * TT * D_MODEL;

    if (tid < 4)  rw_s[tid] = g_rw[tid];
    if (tid == 4) alpha_s   = g_alpha;

    // load halo'd cell tile (130 x 64 floats), T wraps
    for (int i = tid; i < 130*16; i += NTHR){
        int tok = i >> 4, c4 = i & 15;
        int t = (t0 - 1 + tok) & (TT - 1);
        ((float4*)x_s)[i] = ((const float4*)(rowbase + (size_t)t * D_MODEL))[c4];
    }

    // GEMM1: 32 token-groups (4 tokens) x 16 col-lanes (8 cols)
    const int n16 = tid & 15, mg = tid >> 4;
    // GEMM2: 64 token-groups (2 tokens) x 8 col-lanes (8 cols)
    const int n8 = tid & 7,  mg2 = tid >> 3;

    float outa[2][8];
    #pragma unroll
    for (int a = 0; a < 2; a++)
        #pragma unroll
        for (int b = 0; b < 8; b++) outa[a][b] = 0.0f;

    for (int r = 0; r < NRULES; r++){
        // stage rule weights into smem
        {
            const float4* w1g = (const float4*)(rw1 + (size_t)r * K1 * HID);
            #pragma unroll 4
            for (int i = tid; i < (K1*HID)/4; i += NTHR) ((float4*)w1s)[i] = w1g[i];
            const float4* w2g = (const float4*)(rw2 + (size_t)r * HID * D_MODEL);
            #pragma unroll 2
            for (int i = tid; i < (HID*D_MODEL)/4; i += NTHR) ((float4*)w2s)[i] = w2g[i];
        }
        __syncthreads();

        // ---- GEMM1: h[128][128] = gelu(x3[128][192] @ W1 + b1)
        // per thread: m=4 tokens, n=8 cols (4 f32x2 pairs)
        ull acc[4][4];
        #pragma unroll
        for (int a = 0; a < 4; a++){
            #pragma unroll
            for (int b = 0; b < 4; b++) acc[a][b] = 0ULL;
        }

        #pragma unroll
        for (int seg = 0; seg < 3; seg++){
            const int soff = (seg == 0) ? 1 : ((seg == 1) ? 0 : 2);
            const float* xb = x_s + (4*mg + soff) * 64;
            const float* wb = w1s + seg*64*HID + 8*n16;
            for (int kk = 0; kk < 64; kk += 4){
                float4 av[4];
                #pragma unroll
                for (int mi = 0; mi < 4; mi++)
                    av[mi] = *(const float4*)(xb + mi*64 + kk);
                #pragma unroll
                for (int dk = 0; dk < 4; dk++){
                    ulonglong2 b0 = *(const ulonglong2*)(wb + (size_t)(kk+dk)*HID);
                    ulonglong2 b1 = *(const ulonglong2*)(wb + (size_t)(kk+dk)*HID + 4);
                    #pragma unroll
                    for (int mi = 0; mi < 4; mi++){
                        float a = (dk == 0) ? av[mi].x : (dk == 1) ? av[mi].y
                                : (dk == 2) ? av[mi].z : av[mi].w;
                        ull ap = dup2(a);
                        acc[mi][0] = fma2(ap, b0.x, acc[mi][0]);
                        acc[mi][1] = fma2(ap, b0.y, acc[mi][1]);
                        acc[mi][2] = fma2(ap, b1.x, acc[mi][2]);
                        acc[mi][3] = fma2(ap, b1.y, acc[mi][3]);
                    }
                }
            }
        }
        {
            const float4 blo = __ldg((const float4*)(rb1 + r*HID + 8*n16));
            const float4 bhi = __ldg((const float4*)(rb1 + r*HID + 8*n16 + 4));
            #pragma unroll
            for (int mi = 0; mi < 4; mi++){
                float2 p0 = unp2(acc[mi][0]), p1 = unp2(acc[mi][1]);
                float2 p2 = unp2(acc[mi][2]), p3 = unp2(acc[mi][3]);
                float4 h0, h1;
                h0.x = gelu_exact(p0.x + blo.x);
                h0.y = gelu_exact(p0.y + blo.y);
                h0.z = gelu_exact(p1.x + blo.z);
                h0.w = gelu_exact(p1.y + blo.w);
                h1.x = gelu_exact(p2.x + bhi.x);
                h1.y = gelu_exact(p2.y + bhi.y);
                h1.z = gelu_exact(p3.x + bhi.z);
                h1.w = gelu_exact(p3.y + bhi.w);
                float* hp = h_s + (size_t)(4*mg + mi)*HPITCH + 8*n16;
                *(float4*)hp       = h0;
                *(float4*)(hp + 4) = h1;
            }
        }
        __syncthreads();

        // ---- GEMM2: pre[128][64] = h @ W2 ; outa += rw[r]*tanh(pre + b2)
        // per thread: m=2 tokens, n=8 cols
        ull acc2[2][4];
        #pragma unroll
        for (int a = 0; a < 2; a++){
            #pragma unroll
            for (int b = 0; b < 4; b++) acc2[a][b] = 0ULL;
        }
        const float* hb  = h_s + (size_t)(2*mg2) * HPITCH;
        const float* wb2 = w2s + 8*n8;
        for (int kk = 0; kk < HID; kk += 4){
            float4 hv[2];
            #pragma unroll
            for (int mi = 0; mi < 2; mi++)
                hv[mi] = *(const float4*)(hb + (size_t)mi*HPITCH + kk);
            #pragma unroll
            for (int dk = 0; dk < 4; dk++){
                ulonglong2 b0 = *(const ulonglong2*)(wb2 + (size_t)(kk+dk)*D_MODEL);
                ulonglong2 b1 = *(const ulonglong2*)(wb2 + (size_t)(kk+dk)*D_MODEL + 4);
                #pragma unroll
                for (int mi = 0; mi < 2; mi++){
                    float a = (dk == 0) ? hv[mi].x : (dk == 1) ? hv[mi].y
                            : (dk == 2) ? hv[mi].z : hv[mi].w;
                    ull ap = dup2(a);
                    acc2[mi][0] = fma2(ap, b0.x, acc2[mi][0]);
                    acc2[mi][1] = fma2(ap, b0.y, acc2[mi][1]);
                    acc2[mi][2] = fma2(ap, b1.x, acc2[mi][2]);
                    acc2[mi][3] = fma2(ap, b1.y, acc2[mi][3]);
                }
            }
        }
        {
            const float4 clo = __ldg((const float4*)(rb2 + r*D_MODEL + 8*n8));
            const float4 chi = __ldg((const float4*)(rb2 + r*D_MODEL + 8*n8 + 4));
            const float rr = rw_s[r];
            #pragma unroll
            for (int mi = 0; mi < 2; mi++){
                float2 p0 = unp2(acc2[mi][0]), p1 = unp2(acc2[mi][1]);
                float2 p2 = unp2(acc2[mi][2]), p3 = unp2(acc2[mi][3]);
                outa[mi][0] += rr * tanhf(p0.x + clo.x);
                outa[mi][1] += rr * tanhf(p0.y + clo.y);
                outa[mi][2] += rr * tanhf(p1.x + clo.z);
                outa[mi][3] += rr * tanhf(p1.y + clo.w);
                outa[mi][4] += rr * tanhf(p2.x + chi.x);
                outa[mi][5] += rr * tanhf(p2.y + chi.y);
                outa[mi][6] += rr * tanhf(p3.x + chi.z);
                outa[mi][7] += rr * tanhf(p3.y + chi.w);
            }
        }
        __syncthreads();
    }

    // cells = alpha*cells + (1-alpha)*new_cells
    const float al = alpha_s, om = 1.0f - al;
    float* drow = dst + ((size_t)brow*TT + t0) * D_MODEL;
    #pragma unroll
    for (int mi = 0; mi < 2; mi++){
        int m = 2*mg2 + mi;
        const float* xr = x_s + (size_t)(m + 1)*64 + 8*n8;
        float4 cv0 = *(const float4*)xr;
        float4 cv1 = *(const float4*)(xr + 4);
        float4 o0, o1;
        o0.x = al*cv0.x + om*outa[mi][0];
        o0.y = al*cv0.y + om*outa[mi][1];
        o0.z = al*cv0.z + om*outa[mi][2];
        o0.w = al*cv0.w + om*outa[mi][3];
        o1.x = al*cv1.x + om*outa[mi][4];
        o1.y = al*cv1.y + om*outa[mi][5];
        o1.z = al*cv1.z + om*outa[mi][6];
        o1.w = al*cv1.w + om*outa[mi][7];
        float* dp = drow + (size_t)m*D_MODEL + 8*n8;
        *(float4*)dp       = o0;
        *(float4*)(dp + 4) = o1;
    }
}

// ---------------- final LayerNorm ----------------
__global__ void __launch_bounds__(256)
ln_kernel(const float* __restrict__ g, const float* __restrict__ b,
          float* __restrict__ out)
{
    const float* src = ((g_nev - 1) & 1) ? g_buf1 : g_buf0;
    int tok  = blockIdx.x * 8 + (threadIdx.x >> 5);
    int lane = threadIdx.x & 31;
    const float2* p = (const float2*)(src + (size_t)tok * D_MODEL);
    float2 v = p[lane];

    float s = v.x + v.y;
    #pragma unroll
    for (int o = 16; o; o >>= 1) s += __shfl_xor_sync(0xffffffffu, s, o);
    float mu = s * (1.0f/64.0f);

    float dx = v.x - mu, dy = v.y - mu;
    float ss = dx*dx + dy*dy;
    #pragma unroll
    for (int o = 16; o; o >>= 1) ss += __shfl_xor_sync(0xffffffffu, ss, o);
    float rstd = rsqrtf(ss * (1.0f/64.0f) + LN_EPS);

    float2 gg = ((const float2*)g)[lane];
    float2 bb = ((const float2*)b)[lane];
    float2 ov;
    ov.x = dx * rstd * gg.x + bb.x;
    ov.y = dy * rstd * gg.y + bb.y;
    ((float2*)(out + (size_t)tok * D_MODEL))[lane] = ov;
}

// ---------------- launch ----------------
extern "C" void kernel_launch(void* const* d_in, const int* in_sizes, int n_in,
                              void* d_out, int out_size)
{
    const float* cells   = (const float*)d_in[0];
    const float* c_state = (const float*)d_in[1];
    const float* rule_w1 = (const float*)d_in[2];
    const float* rule_b1 = (const float*)d_in[3];
    const float* rule_w2 = (const float*)d_in[4];
    const float* rule_b2 = (const float*)d_in[5];
    const float* sel_w1  = (const float*)d_in[6];
    const float* sel_b1  = (const float*)d_in[7];
    const float* sel_w2  = (const float*)d_in[8];
    const float* sel_b2  = (const float*)d_in[9];
    const float* st_w1   = (const float*)d_in[10];
    const float* st_b1   = (const float*)d_in[11];
    const float* st_w2   = (const float*)d_in[12];
    const float* st_b2   = (const float*)d_in[13];
    const float* res_w1  = (const float*)d_in[14];
    const float* res_b1  = (const float*)d_in[15];
    const float* res_w2  = (const float*)d_in[16];
    const float* res_b2  = (const float*)d_in[17];
    const float* ln_g    = (const float*)d_in[18];
    const float* ln_b    = (const float*)d_in[19];

    cudaFuncSetAttribute(step_kernel,
                         cudaFuncAttributeMaxDynamicSharedMemorySize, SMEM_BYTES);

    control_kernel<<<1, 128>>>(c_state,
                               sel_w1, sel_b1, sel_w2, sel_b2,
                               st_w1,  st_b1,  st_w2,  st_b2,
                               res_w1, res_b1, res_w2, res_b2);

    for (int j = 0; j < 8; j++)
        step_kernel<<<NBLK, NTHR, SMEM_BYTES>>>(cells, rule_w1, rule_b1,
                                                rule_w2, rule_b2, j);

    ln_kernel<<<NTOK/8, 256>>>(ln_g, ln_b, (float*)d_out);
}

// round 4
// speedup vs baseline: 1.0003x; 1.0003x over previous
#include <cuda_runtime.h>
#include <cstdint>
#include <math.h>

// ---------------- problem constants ----------------
#define D_MODEL 64
#define HID     128
#define NRULES  4
#define K1      192              // 3*D_MODEL
#define BB      32
#define TT      8192
#define NTOK    (BB*TT)          // 262144
#define TILE    128              // tokens per block
#define NBLK    (NTOK/TILE)      // 2048
#define NTHR    512
#define LN_EPS  1e-5f

// ---------------- smem layout (floats) ----------------
#define OFF_X   0
#define SZ_X    (130*64)         // halo tile: tokens t0-1 .. t0+128
#define OFF_W1  (OFF_X + SZ_X)
#define SZ_W1   (K1*HID)         // 24576
#define OFF_W2  (OFF_W1 + SZ_W1)
#define SZ_W2   (HID*D_MODEL)    // 8192
#define HPITCH  132
#define OFF_H   (OFF_W2 + SZ_W2)
#define SZ_H    (128*HPITCH)     // 16896
#define SMEM_FLOATS (OFF_H + SZ_H)         // 57984
#define SMEM_BYTES  (SMEM_FLOATS*4)        // 231936 B

// ---------------- device state ----------------
__device__ float g_rw[4];
__device__ float g_alpha;
__device__ int   g_nev;
__device__ float g_buf0[(size_t)NTOK*D_MODEL];
__device__ float g_buf1[(size_t)NTOK*D_MODEL];

// ---------------- packed f32x2 helpers ----------------
typedef unsigned long long ull;

__device__ __forceinline__ ull fma2(ull a, ull b, ull c){
    ull d; asm("fma.rn.f32x2 %0, %1, %2, %3;" : "=l"(d) : "l"(a), "l"(b), "l"(c)); return d;
}
__device__ __forceinline__ ull dup2(float a){
    ull d; asm("mov.b64 %0, {%1, %2};" : "=l"(d) : "f"(a), "f"(a)); return d;
}
__device__ __forceinline__ float2 unp2(ull v){
    float2 r; asm("mov.b64 {%0, %1}, %2;" : "=f"(r.x), "=f"(r.y) : "l"(v)); return r;
}

__device__ __forceinline__ float gelu_exact(float x){
    return 0.5f * x * (1.0f + erff(x * 0.7071067811865475f));
}

// ---------------- control kernel ----------------
__global__ void control_kernel(
    const float* __restrict__ c,
    const float* __restrict__ p_sw1, const float* __restrict__ p_sb1,
    const float* __restrict__ p_sw2, const float* __restrict__ p_sb2,
    const float* __restrict__ p_tw1, const float* __restrict__ p_tb1,
    const float* __restrict__ p_tw2, const float* __restrict__ p_tb2,
    const float* __restrict__ p_rw1, const float* __restrict__ p_rb1,
    const float* __restrict__ p_rw2, const float* __restrict__ p_rb2)
{
    __shared__ float cs[128];
    __shared__ float h1[64];
    __shared__ float h2[32];
    __shared__ float h3[32];
    int t = threadIdx.x;
    if (t < 128) cs[t] = c[t];
    __syncthreads();

    if (t < 64){
        float a = p_sb1[t];
        for (int k = 0; k < 128; k++) a += cs[k] * p_sw1[k*64 + t];
        h1[t] = gelu_exact(a);
    } else if (t < 96){
        int i = t - 64;
        float a = p_tb1[i];
        for (int k = 0; k < 128; k++) a += cs[k] * p_tw1[k*32 + i];
        h2[i] = gelu_exact(a);
    } else {
        int i = t - 96;
        float a = p_rb1[i];
        for (int k = 0; k < 128; k++) a += cs[k] * p_rw1[k*32 + i];
        h3[i] = gelu_exact(a);
    }
    __syncthreads();

    if (t == 0){
        float l[4]; float mx = -1e30f;
        for (int r = 0; r < 4; r++){
            float a = p_sb2[r];
            for (int i = 0; i < 64; i++) a += h1[i] * p_sw2[i*4 + r];
            l[r] = a; mx = fmaxf(mx, a);
        }
        float s = 0.0f;
        for (int r = 0; r < 4; r++){ l[r] = expf(l[r] - mx); s += l[r]; }
        for (int r = 0; r < 4; r++) g_rw[r] = l[r] / s;
    }
    if (t == 1){
        float l[7]; float mx = -1e30f;
        for (int jj = 0; jj < 7; jj++){
            float a = p_tb2[jj];
            for (int i = 0; i < 32; i++) a += h2[i] * p_tw2[i*7 + jj];
            l[jj] = a; mx = fmaxf(mx, a);
        }
        float s = 0.0f;
        for (int jj = 0; jj < 7; jj++){ l[jj] = expf(l[jj] - mx); s += l[jj]; }
        const float steps[7] = {2.0f,3.0f,4.0f,5.0f,6.0f,7.0f,8.0f};
        float nf = 0.0f;
        for (int jj = 0; jj < 7; jj++) nf += (l[jj] / s) * steps[jj];
        int n = (int)(nf + 0.5f);
        if (n < 2) n = 2;
        if (n > 8) n = 8;
        g_nev = n;
    }
    if (t == 2){
        float v = p_rb2[0];
        for (int i = 0; i < 32; i++) v += h3[i] * p_rw2[i];
        g_alpha = 0.1f + 0.8f / (1.0f + expf(-v));
    }
}

// ---------------- evolve step ----------------
__global__ void __launch_bounds__(NTHR, 1)
step_kernel(const float* __restrict__ cells_in,
            const float* __restrict__ rw1, const float* __restrict__ rb1,
            const float* __restrict__ rw2, const float* __restrict__ rb2,
            int j)
{
    if (j >= g_nev) return;

    extern __shared__ float sm[];
    float* x_s  = sm + OFF_X;
    float* w1s  = sm + OFF_W1;
    float* w2s  = sm + OFF_W2;
    float* h_s  = sm + OFF_H;
    __shared__ float rw_s[4];
    __shared__ float alpha_s;

    const float* src = (j == 0) ? cells_in : ((j & 1) ? g_buf0 : g_buf1);
    float*       dst = (j & 1) ? g_buf1 : g_buf0;

    const int tid  = threadIdx.x;
    const int brow = blockIdx.x >> 6;
    const int t0   = (blockIdx.x & 63) << 7;
    const float* rowbase = src + (size_t)brow * TT * D_MODEL;

    if (tid < 4)  rw_s[tid] = g_rw[tid];
    if (tid == 4) alpha_s   = g_alpha;

    // load halo'd cell tile (130 x 64 floats), T wraps
    for (int i = tid; i < 130*16; i += NTHR){
        int tok = i >> 4, c4 = i & 15;
        int t = (t0 - 1 + tok) & (TT - 1);
        ((float4*)x_s)[i] = ((const float4*)(rowbase + (size_t)t * D_MODEL))[c4];
    }

    // GEMM1: 32 token-groups (4 tokens) x 16 col-lanes (8 cols)
    const int n16 = tid & 15, mg = tid >> 4;
    // GEMM2: 64 token-groups (2 tokens) x 8 col-lanes (8 cols)
    const int n8 = tid & 7,  mg2 = tid >> 3;

    float outa[2][8];
    #pragma unroll
    for (int a = 0; a < 2; a++)
        #pragma unroll
        for (int b = 0; b < 8; b++) outa[a][b] = 0.0f;

    for (int r = 0; r < NRULES; r++){
        // stage rule weights into smem
        {
            const float4* w1g = (const float4*)(rw1 + (size_t)r * K1 * HID);
            #pragma unroll 4
            for (int i = tid; i < (K1*HID)/4; i += NTHR) ((float4*)w1s)[i] = w1g[i];
            const float4* w2g = (const float4*)(rw2 + (size_t)r * HID * D_MODEL);
            #pragma unroll 2
            for (int i = tid; i < (HID*D_MODEL)/4; i += NTHR) ((float4*)w2s)[i] = w2g[i];
        }
        __syncthreads();

        // ---- GEMM1: h[128][128] = gelu(x3[128][192] @ W1 + b1)
        // per thread: m=4 tokens, n=8 cols (4 f32x2 pairs)
        ull acc[4][4];
        #pragma unroll
        for (int a = 0; a < 4; a++){
            #pragma unroll
            for (int b = 0; b < 4; b++) acc[a][b] = 0ULL;
        }

        #pragma unroll
        for (int seg = 0; seg < 3; seg++){
            const int soff = (seg == 0) ? 1 : ((seg == 1) ? 0 : 2);
            const float* xb = x_s + (4*mg + soff) * 64;
            const float* wb = w1s + seg*64*HID + 8*n16;
            for (int kk = 0; kk < 64; kk += 4){
                float4 av[4];
                #pragma unroll
                for (int mi = 0; mi < 4; mi++)
                    av[mi] = *(const float4*)(xb + mi*64 + kk);
                #pragma unroll
                for (int dk = 0; dk < 4; dk++){
                    ulonglong2 b0 = *(const ulonglong2*)(wb + (size_t)(kk+dk)*HID);
                    ulonglong2 b1 = *(const ulonglong2*)(wb + (size_t)(kk+dk)*HID + 4);
                    #pragma unroll
                    for (int mi = 0; mi < 4; mi++){
                        float a = (dk == 0) ? av[mi].x : (dk == 1) ? av[mi].y
                                : (dk == 2) ? av[mi].z : av[mi].w;
                        ull ap = dup2(a);
                        acc[mi][0] = fma2(ap, b0.x, acc[mi][0]);
                        acc[mi][1] = fma2(ap, b0.y, acc[mi][1]);
                        acc[mi][2] = fma2(ap, b1.x, acc[mi][2]);
                        acc[mi][3] = fma2(ap, b1.y, acc[mi][3]);
                    }
                }
            }
        }
        {
            const float4 blo = __ldg((const float4*)(rb1 + r*HID + 8*n16));
            const float4 bhi = __ldg((const float4*)(rb1 + r*HID + 8*n16 + 4));
            #pragma unroll
            for (int mi = 0; mi < 4; mi++){
                float2 p0 = unp2(acc[mi][0]), p1 = unp2(acc[mi][1]);
                float2 p2 = unp2(acc[mi][2]), p3 = unp2(acc[mi][3]);
                float4 h0, h1;
                h0.x = gelu_exact(p0.x + blo.x);
                h0.y = gelu_exact(p0.y + blo.y);
                h0.z = gelu_exact(p1.x + blo.z);
                h0.w = gelu_exact(p1.y + blo.w);
                h1.x = gelu_exact(p2.x + bhi.x);
                h1.y = gelu_exact(p2.y + bhi.y);
                h1.z = gelu_exact(p3.x + bhi.z);
                h1.w = gelu_exact(p3.y + bhi.w);
                float* hp = h_s + (size_t)(4*mg + mi)*HPITCH + 8*n16;
                *(float4*)hp       = h0;
                *(float4*)(hp + 4) = h1;
            }
        }
        __syncthreads();

        // ---- GEMM2: pre[128][64] = h @ W2 ; outa += rw[r]*tanh(pre + b2)
        // per thread: m=2 tokens, n=8 cols
        ull acc2[2][4];
        #pragma unroll
        for (int a = 0; a < 2; a++){
            #pragma unroll
            for (int b = 0; b < 4; b++) acc2[a][b] = 0ULL;
        }
        const float* hb  = h_s + (size_t)(2*mg2) * HPITCH;
        const float* wb2 = w2s + 8*n8;
        for (int kk = 0; kk < HID; kk += 4){
            float4 hv[2];
            #pragma unroll
            for (int mi = 0; mi < 2; mi++)
                hv[mi] = *(const float4*)(hb + (size_t)mi*HPITCH + kk);
            #pragma unroll
            for (int dk = 0; dk < 4; dk++){
                ulonglong2 b0 = *(const ulonglong2*)(wb2 + (size_t)(kk+dk)*D_MODEL);
                ulonglong2 b1 = *(const ulonglong2*)(wb2 + (size_t)(kk+dk)*D_MODEL + 4);
                #pragma unroll
                for (int mi = 0; mi < 2; mi++){
                    float a = (dk == 0) ? hv[mi].x : (dk == 1) ? hv[mi].y
                            : (dk == 2) ? hv[mi].z : hv[mi].w;
                    ull ap = dup2(a);
                    acc2[mi][0] = fma2(ap, b0.x, acc2[mi][0]);
                    acc2[mi][1] = fma2(ap, b0.y, acc2[mi][1]);
                    acc2[mi][2] = fma2(ap, b1.x, acc2[mi][2]);
                    acc2[mi][3] = fma2(ap, b1.y, acc2[mi][3]);
                }
            }
        }
        {
            const float4 clo = __ldg((const float4*)(rb2 + r*D_MODEL + 8*n8));
            const float4 chi = __ldg((const float4*)(rb2 + r*D_MODEL + 8*n8 + 4));
            const float rr = rw_s[r];
            #pragma unroll
            for (int mi = 0; mi < 2; mi++){
                float2 p0 = unp2(acc2[mi][0]), p1 = unp2(acc2[mi][1]);
                float2 p2 = unp2(acc2[mi][2]), p3 = unp2(acc2[mi][3]);
                outa[mi][0] += rr * tanhf(p0.x + clo.x);
                outa[mi][1] += rr * tanhf(p0.y + clo.y);
                outa[mi][2] += rr * tanhf(p1.x + clo.z);
                outa[mi][3] += rr * tanhf(p1.y + clo.w);
                outa[mi][4] += rr * tanhf(p2.x + chi.x);
                outa[mi][5] += rr * tanhf(p2.y + chi.y);
                outa[mi][6] += rr * tanhf(p3.x + chi.z);
                outa[mi][7] += rr * tanhf(p3.y + chi.w);
            }
        }
        __syncthreads();
    }

    // cells = alpha*cells + (1-alpha)*new_cells
    const float al = alpha_s, om = 1.0f - al;
    float* drow = dst + ((size_t)brow*TT + t0) * D_MODEL;
    #pragma unroll
    for (int mi = 0; mi < 2; mi++){
        int m = 2*mg2 + mi;
        const float* xr = x_s + (size_t)(m + 1)*64 + 8*n8;
        float4 cv0 = *(const float4*)xr;
        float4 cv1 = *(const float4*)(xr + 4);
        float4 o0, o1;
        o0.x = al*cv0.x + om*outa[mi][0];
        o0.y = al*cv0.y + om*outa[mi][1];
        o0.z = al*cv0.z + om*outa[mi][2];
        o0.w = al*cv0.w + om*outa[mi][3];
        o1.x = al*cv1.x + om*outa[mi][4];
        o1.y = al*cv1.y + om*outa[mi][5];
        o1.z = al*cv1.z + om*outa[mi][6];
        o1.w = al*cv1.w + om*outa[mi][7];
        float* dp = drow + (size_t)m*D_MODEL + 8*n8;
        *(float4*)dp       = o0;
        *(float4*)(dp + 4) = o1;
    }
}

// ---------------- final LayerNorm ----------------
__global__ void __launch_bounds__(256)
ln_kernel(const float* __restrict__ g, const float* __restrict__ b,
          float* __restrict__ out)
{
    const float* src = ((g_nev - 1) & 1) ? g_buf1 : g_buf0;
    int tok  = blockIdx.x * 8 + (threadIdx.x >> 5);
    int lane = threadIdx.x & 31;
    const float2* p = (const float2*)(src + (size_t)tok * D_MODEL);
    float2 v = p[lane];

    float s = v.x + v.y;
    #pragma unroll
    for (int o = 16; o; o >>= 1) s += __shfl_xor_sync(0xffffffffu, s, o);
    float mu = s * (1.0f/64.0f);

    float dx = v.x - mu, dy = v.y - mu;
    float ss = dx*dx + dy*dy;
    #pragma unroll
    for (int o = 16; o; o >>= 1) ss += __shfl_xor_sync(0xffffffffu, ss, o);
    float rstd = rsqrtf(ss * (1.0f/64.0f) + LN_EPS);

    float2 gg = ((const float2*)g)[lane];
    float2 bb = ((const float2*)b)[lane];
    float2 ov;
    ov.x = dx * rstd * gg.x + bb.x;
    ov.y = dy * rstd * gg.y + bb.y;
    ((float2*)(out + (size_t)tok * D_MODEL))[lane] = ov;
}

// ---------------- launch ----------------
extern "C" void kernel_launch(void* const* d_in, const int* in_sizes, int n_in,
                              void* d_out, int out_size)
{
    const float* cells   = (const float*)d_in[0];
    const float* c_state = (const float*)d_in[1];
    const float* rule_w1 = (const float*)d_in[2];
    const float* rule_b1 = (const float*)d_in[3];
    const float* rule_w2 = (const float*)d_in[4];
    const float* rule_b2 = (const float*)d_in[5];
    const float* sel_w1  = (const float*)d_in[6];
    const float* sel_b1  = (const float*)d_in[7];
    const float* sel_w2  = (const float*)d_in[8];
    const float* sel_b2  = (const float*)d_in[9];
    const float* st_w1   = (const float*)d_in[10];
    const float* st_b1   = (const float*)d_in[11];
    const float* st_w2   = (const float*)d_in[12];
    const float* st_b2   = (const float*)d_in[13];
    const float* res_w1  = (const float*)d_in[14];
    const float* res_b1  = (const float*)d_in[15];
    const float* res_w2  = (const float*)d_in[16];
    const float* res_b2  = (const float*)d_in[17];
    const float* ln_g    = (const float*)d_in[18];
    const float* ln_b    = (const float*)d_in[19];

    cudaFuncSetAttribute(step_kernel,
                         cudaFuncAttributeMaxDynamicSharedMemorySize, SMEM_BYTES);

    control_kernel<<<1, 128>>>(c_state,
                               sel_w1, sel_b1, sel_w2, sel_b2,
                               st_w1,  st_b1,  st_w2,  st_b2,
                               res_w1, res_b1, res_w2, res_b2);

    for (int j = 0; j < 8; j++)
        step_kernel<<<NBLK, NTHR, SMEM_BYTES>>>(cells, rule_w1, rule_b1,
                                                rule_w2, rule_b2, j);

    ln_kernel<<<NTOK/8, 256>>>(ln_g, ln_b, (float*)d_out);
}

// round 6
// speedup vs baseline: 3.2489x; 3.2480x over previous
#include <cuda_runtime.h>
#include <cuda_bf16.h>
#include <cstdint>
#include <math.h>

#define D_MODEL 64
#define HID     128
#define NRULES  4
#define K1      192
#define TT      8192
#define NTOK    (32*TT)
#define NBLK    (NTOK/128)       // 2048 CTAs, 128 tokens each
#define NTHR    256
#define LN_EPS  1e-5f

// ---- smem layout (float indices) ----
// cells halo fp32: 130 rows x pitch 68            [0 .. 8840)
// h fp32:          128 rows x pitch 132           [8840 .. 25736)
// W hi packed bf16x2 (u32): 4608                  [25736 .. 30344)
// W lo packed bf16x2 (u32): 4608                  [30344 .. 34952)
#define OFF_C   0
#define CPITCH  68
#define OFF_H   8840
#define HPITCH  132
#define OFF_WH  25736
#define OFF_WL  30344
#define SMEM_FLOATS 34952
#define SMEM_BYTES  (SMEM_FLOATS*4)   // 139808

// W1 staged per 64-k segment: 32 kp-rows x 128 n, pitch 136 (bank 8*tig+g)
// W2 staged whole:            64 kp-rows x 64 n,  pitch 72  (bank 8*tig+g)
#define W1P 136
#define W2P 72

__device__ float g_rw[4];
__device__ float g_alpha;
__device__ int   g_nev;
__device__ float g_buf0[(size_t)NTOK*D_MODEL];
__device__ float g_buf1[(size_t)NTOK*D_MODEL];

__device__ __forceinline__ float gelu_exact(float x){
    return 0.5f * x * (1.0f + erff(x * 0.7071067811865475f));
}

// split float pair into bf16x2 hi and bf16x2 lo packs
__device__ __forceinline__ void pack_hilo(float2 v, uint32_t& hi, uint32_t& lo){
    __nv_bfloat162 hb = __float22bfloat162_rn(v);
    float2 lv;
    lv.x = v.x - __bfloat162float(hb.x);
    lv.y = v.y - __bfloat162float(hb.y);
    __nv_bfloat162 lb = __float22bfloat162_rn(lv);
    hi = *(uint32_t*)&hb;
    lo = *(uint32_t*)&lb;
}

__device__ __forceinline__ void mma_bf16(float* d,
    uint32_t a0, uint32_t a1, uint32_t a2, uint32_t a3,
    uint32_t b0, uint32_t b1)
{
    asm volatile(
        "mma.sync.aligned.m16n8k16.row.col.f32.bf16.bf16.f32 "
        "{%0,%1,%2,%3},{%4,%5,%6,%7},{%8,%9},{%0,%1,%2,%3};"
        : "+f"(d[0]), "+f"(d[1]), "+f"(d[2]), "+f"(d[3])
        : "r"(a0), "r"(a1), "r"(a2), "r"(a3), "r"(b0), "r"(b1));
}

// ---------------- control kernel ----------------
__global__ void control_kernel(
    const float* __restrict__ c,
    const float* __restrict__ sw1, const float* __restrict__ sb1,
    const float* __restrict__ sw2, const float* __restrict__ sb2,
    const float* __restrict__ tw1, const float* __restrict__ tb1,
    const float* __restrict__ tw2, const float* __restrict__ tb2,
    const float* __restrict__ qw1, const float* __restrict__ qb1,
    const float* __restrict__ qw2, const float* __restrict__ qb2)
{
    __shared__ float cs[128], h1[64], h2[32], h3[32];
    int t = threadIdx.x;
    if (t < 128) cs[t] = c[t];
    __syncthreads();
    if (t < 64){
        float a = sb1[t];
        for (int k = 0; k < 128; k++) a += cs[k] * sw1[k*64 + t];
        h1[t] = gelu_exact(a);
    } else if (t < 96){
        int i = t - 64; float a = tb1[i];
        for (int k = 0; k < 128; k++) a += cs[k] * tw1[k*32 + i];
        h2[i] = gelu_exact(a);
    } else {
        int i = t - 96; float a = qb1[i];
        for (int k = 0; k < 128; k++) a += cs[k] * qw1[k*32 + i];
        h3[i] = gelu_exact(a);
    }
    __syncthreads();
    if (t == 0){
        float l[4], mx = -1e30f;
        for (int r = 0; r < 4; r++){
            float a = sb2[r];
            for (int i = 0; i < 64; i++) a += h1[i] * sw2[i*4 + r];
            l[r] = a; mx = fmaxf(mx, a);
        }
        float s = 0.f;
        for (int r = 0; r < 4; r++){ l[r] = expf(l[r]-mx); s += l[r]; }
        for (int r = 0; r < 4; r++) g_rw[r] = l[r]/s;
    }
    if (t == 1){
        float l[7], mx = -1e30f;
        for (int q = 0; q < 7; q++){
            float a = tb2[q];
            for (int i = 0; i < 32; i++) a += h2[i] * tw2[i*7 + q];
            l[q] = a; mx = fmaxf(mx, a);
        }
        float s = 0.f;
        for (int q = 0; q < 7; q++){ l[q] = expf(l[q]-mx); s += l[q]; }
        float nf = 0.f;
        for (int q = 0; q < 7; q++) nf += (l[q]/s) * (float)(q+2);
        int n = (int)(nf + 0.5f);
        g_nev = n < 2 ? 2 : (n > 8 ? 8 : n);
    }
    if (t == 2){
        float v = qb2[0];
        for (int i = 0; i < 32; i++) v += h3[i] * qw2[i];
        g_alpha = 0.1f + 0.8f / (1.0f + expf(-v));
    }
}

// ---------------- evolve step: mma.sync bf16 hi/lo (3-term) ----------------
__global__ void __launch_bounds__(NTHR, 1)
step_kernel(const float* __restrict__ cells_in,
            const float* __restrict__ rw1, const float* __restrict__ rb1,
            const float* __restrict__ rw2, const float* __restrict__ rb2,
            int j)
{
    if (j >= g_nev) return;

    extern __shared__ float sm[];
    float*    cs = sm + OFF_C;
    float*    hs = sm + OFF_H;
    uint32_t* wh = (uint32_t*)(sm + OFF_WH);
    uint32_t* wl = (uint32_t*)(sm + OFF_WL);

    const float* src = (j == 0) ? cells_in : ((j & 1) ? g_buf0 : g_buf1);
    float*       dst = (j & 1) ? g_buf1 : g_buf0;

    const int tid  = threadIdx.x;
    const int w    = tid >> 5;
    const int lane = tid & 31;
    const int g    = lane >> 2;         // row group 0..7
    const int tig  = lane & 3;          // thread-in-group
    const int m0   = w * 16;            // warp's 16-row M tile

    const int brow = blockIdx.x >> 6;
    const int t0   = (blockIdx.x & 63) << 7;
    const float* rowbase = src + (size_t)brow * TT * D_MODEL;

    // load halo'd cells (fp32): rows t0-1 .. t0+128
    for (int i = tid; i < 130*16; i += NTHR){
        int row = i >> 4, c4 = i & 15;
        int t = (t0 - 1 + row) & (TT - 1);
        ((float4*)cs)[row*(CPITCH/4) + c4] =
            ((const float4*)(rowbase + (size_t)t * D_MODEL))[c4];
    }
    __syncthreads();

    float outa[32];
    #pragma unroll
    for (int i = 0; i < 32; i++) outa[i] = 0.0f;

    for (int r = 0; r < NRULES; r++){
        // ================= GEMM1: C1[128x128] = X3[128x192] @ W1 =================
        float acc[16][4];
        #pragma unroll
        for (int a = 0; a < 16; a++){
            acc[a][0] = 0.f; acc[a][1] = 0.f; acc[a][2] = 0.f; acc[a][3] = 0.f;
        }

        for (int seg = 0; seg < 3; seg++){
            // stage W1 segment [64k x 128n] -> packed kp x n (hi/lo), pitch 136
            {
                const float* w1g = rw1 + (size_t)r * K1 * HID + (size_t)seg * 64 * HID;
                #pragma unroll
                for (int it = 0; it < 16; it++){
                    int e  = it*NTHR + tid;       // 0..4095
                    int kp = e >> 7, n = e & 127;
                    float2 v;
                    v.x = __ldg(w1g + (size_t)(2*kp)   * HID + n);
                    v.y = __ldg(w1g + (size_t)(2*kp+1) * HID + n);
                    uint32_t hi, lo;
                    pack_hilo(v, hi, lo);
                    wh[kp*W1P + n] = hi;
                    wl[kp*W1P + n] = lo;
                }
            }
            __syncthreads();

            const int soff = (seg == 0) ? 1 : ((seg == 1) ? 0 : 2);
            const float* ra = cs + (size_t)(m0 + soff + g) * CPITCH;
            const float* rb = cs + (size_t)(m0 + soff + g + 8) * CPITCH;

            #pragma unroll
            for (int kt = 0; kt < 4; kt++){
                int kc = kt*16 + 2*tig;
                uint32_t ah0,ah1,ah2,ah3, al0,al1,al2,al3;
                pack_hilo(*(const float2*)(ra + kc),     ah0, al0);
                pack_hilo(*(const float2*)(rb + kc),     ah1, al1);
                pack_hilo(*(const float2*)(ra + kc + 8), ah2, al2);
                pack_hilo(*(const float2*)(rb + kc + 8), ah3, al3);
                const int kr0 = (kt*8 + tig)*W1P;
                const int kr1 = (kt*8 + tig + 4)*W1P;
                #pragma unroll
                for (int nt = 0; nt < 16; nt++){
                    int nc = nt*8 + g;
                    uint32_t bh0 = wh[kr0 + nc], bh1 = wh[kr1 + nc];
                    uint32_t bl0 = wl[kr0 + nc], bl1 = wl[kr1 + nc];
                    mma_bf16(acc[nt], ah0,ah1,ah2,ah3, bh0,bh1);
                    mma_bf16(acc[nt], al0,al1,al2,al3, bh0,bh1);
                    mma_bf16(acc[nt], ah0,ah1,ah2,ah3, bl0,bl1);
                }
            }
            __syncthreads();   // before next segment staging overwrites W buf
        }

        // epilogue1: h = gelu(C1 + b1) -> hs (fp32)
        {
            float* hra = hs + (size_t)(m0 + g) * HPITCH;
            float* hrb = hs + (size_t)(m0 + g + 8) * HPITCH;
            #pragma unroll
            for (int nt = 0; nt < 16; nt++){
                int c = nt*8 + 2*tig;
                const float2 b = __ldg((const float2*)(rb1 + r*HID + c));
                float2 va, vb;
                va.x = gelu_exact(acc[nt][0] + b.x);
                va.y = gelu_exact(acc[nt][1] + b.y);
                vb.x = gelu_exact(acc[nt][2] + b.x);
                vb.y = gelu_exact(acc[nt][3] + b.y);
                *(float2*)(hra + c) = va;
                *(float2*)(hrb + c) = vb;
            }
        }

        // stage W2 [128k x 64n] -> packed 64kp x 64n hi/lo, pitch 72
        {
            const float* w2g = rw2 + (size_t)r * HID * D_MODEL;
            #pragma unroll
            for (int it = 0; it < 16; it++){
                int e  = it*NTHR + tid;          // 0..4095
                int kp = e >> 6, n = e & 63;
                float2 v;
                v.x = __ldg(w2g + (size_t)(2*kp)   * D_MODEL + n);
                v.y = __ldg(w2g + (size_t)(2*kp+1) * D_MODEL + n);
                uint32_t hi, lo;
                pack_hilo(v, hi, lo);
                wh[kp*W2P + n] = hi;
                wl[kp*W2P + n] = lo;
            }
        }
        __syncthreads();

        // ================= GEMM2: C2[128x64] = h[128x128] @ W2 =================
        float acc2[8][4];
        #pragma unroll
        for (int a = 0; a < 8; a++){
            acc2[a][0] = 0.f; acc2[a][1] = 0.f; acc2[a][2] = 0.f; acc2[a][3] = 0.f;
        }
        {
            const float* ra = hs + (size_t)(m0 + g) * HPITCH;
            const float* rb = hs + (size_t)(m0 + g + 8) * HPITCH;
            #pragma unroll
            for (int kt = 0; kt < 8; kt++){
                int kc = kt*16 + 2*tig;
                uint32_t ah0,ah1,ah2,ah3, al0,al1,al2,al3;
                pack_hilo(*(const float2*)(ra + kc),     ah0, al0);
                pack_hilo(*(const float2*)(rb + kc),     ah1, al1);
                pack_hilo(*(const float2*)(ra + kc + 8), ah2, al2);
                pack_hilo(*(const float2*)(rb + kc + 8), ah3, al3);
                const int kr0 = (kt*8 + tig)*W2P;
                const int kr1 = (kt*8 + tig + 4)*W2P;
                #pragma unroll
                for (int nt = 0; nt < 8; nt++){
                    int nc = nt*8 + g;
                    uint32_t bh0 = wh[kr0 + nc], bh1 = wh[kr1 + nc];
                    uint32_t bl0 = wl[kr0 + nc], bl1 = wl[kr1 + nc];
                    mma_bf16(acc2[nt], ah0,ah1,ah2,ah3, bh0,bh1);
                    mma_bf16(acc2[nt], al0,al1,al2,al3, bh0,bh1);
                    mma_bf16(acc2[nt], ah0,ah1,ah2,ah3, bl0,bl1);
                }
            }
        }

        // epilogue2: outa += rw[r] * tanh(C2 + b2)
        {
            const float rr = g_rw[r];
            #pragma unroll
            for (int nt = 0; nt < 8; nt++){
                int c = nt*8 + 2*tig;
                const float2 b = __ldg((const float2*)(rb2 + r*D_MODEL + c));
                outa[nt*4+0] += rr * tanhf(acc2[nt][0] + b.x);
                outa[nt*4+1] += rr * tanhf(acc2[nt][1] + b.y);
                outa[nt*4+2] += rr * tanhf(acc2[nt][2] + b.x);
                outa[nt*4+3] += rr * tanhf(acc2[nt][3] + b.y);
            }
        }
        __syncthreads();   // h / W buffers reused next rule
    }

    // residual mix + store: rows m0+g and m0+g+8
    {
        const float al = g_alpha, om = 1.0f - al;
        const float* cra = cs + (size_t)(m0 + 1 + g) * CPITCH;
        const float* crb = cs + (size_t)(m0 + 1 + g + 8) * CPITCH;
        float* da = dst + ((size_t)brow*TT + t0 + m0 + g) * D_MODEL;
        float* db = dst + ((size_t)brow*TT + t0 + m0 + g + 8) * D_MODEL;
        #pragma unroll
        for (int nt = 0; nt < 8; nt++){
            int c = nt*8 + 2*tig;
            float2 cva = *(const float2*)(cra + c);
            float2 cvb = *(const float2*)(crb + c);
            float2 oa, ob;
            oa.x = al*cva.x + om*outa[nt*4+0];
            oa.y = al*cva.y + om*outa[nt*4+1];
            ob.x = al*cvb.x + om*outa[nt*4+2];
            ob.y = al*cvb.y + om*outa[nt*4+3];
            *(float2*)(da + c) = oa;
            *(float2*)(db + c) = ob;
        }
    }
}

// ---------------- final LayerNorm ----------------
__global__ void __launch_bounds__(256)
ln_kernel(const float* __restrict__ g, const float* __restrict__ b,
          float* __restrict__ out)
{
    const float* src = ((g_nev - 1) & 1) ? g_buf1 : g_buf0;
    int tok  = blockIdx.x * 8 + (threadIdx.x >> 5);
    int lane = threadIdx.x & 31;
    float2 v = ((const float2*)(src + (size_t)tok * D_MODEL))[lane];
    float s = v.x + v.y;
    #pragma unroll
    for (int o = 16; o; o >>= 1) s += __shfl_xor_sync(0xffffffffu, s, o);
    float mu = s * (1.0f/64.0f);
    float dx = v.x - mu, dy = v.y - mu;
    float ss = dx*dx + dy*dy;
    #pragma unroll
    for (int o = 16; o; o >>= 1) ss += __shfl_xor_sync(0xffffffffu, ss, o);
    float rstd = rsqrtf(ss * (1.0f/64.0f) + LN_EPS);
    float2 gg = ((const float2*)g)[lane];
    float2 bb = ((const float2*)b)[lane];
    float2 ov;
    ov.x = dx * rstd * gg.x + bb.x;
    ov.y = dy * rstd * gg.y + bb.y;
    ((float2*)(out + (size_t)tok * D_MODEL))[lane] = ov;
}

// ---------------- launch ----------------
extern "C" void kernel_launch(void* const* d_in, const int* in_sizes, int n_in,
                              void* d_out, int out_size)
{
    const float* cells = (const float*)d_in[0];
    cudaFuncSetAttribute(step_kernel,
                         cudaFuncAttributeMaxDynamicSharedMemorySize, SMEM_BYTES);
    control_kernel<<<1, 128>>>((const float*)d_in[1],
        (const float*)d_in[6],  (const float*)d_in[7],
        (const float*)d_in[8],  (const float*)d_in[9],
        (const float*)d_in[10], (const float*)d_in[11],
        (const float*)d_in[12], (const float*)d_in[13],
        (const float*)d_in[14], (const float*)d_in[15],
        (const float*)d_in[16], (const float*)d_in[17]);
    for (int j = 0; j < 8; j++)
        step_kernel<<<NBLK, NTHR, SMEM_BYTES>>>(cells,
            (const float*)d_in[2], (const float*)d_in[3],
            (const float*)d_in[4], (const float*)d_in[5], j);
    ln_kernel<<<NTOK/8, 256>>>((const float*)d_in[18], (const float*)d_in[19],
                               (float*)d_out);
}

// round 8
// speedup vs baseline: 3.2499x; 1.0003x over previous
#include <cuda_runtime.h>
#include <cuda_bf16.h>
#include <cstdint>
#include <math.h>

#define D_MODEL 64
#define HID     128
#define NRULES  4
#define K1      192
#define TT      8192
#define NTOK    (32*TT)
#define NBLK    (NTOK/128)       // 2048 CTAs, 128 tokens each
#define NTHR    256
#define LN_EPS  1e-5f

// ---- smem layout ----
// cells halo fp32: 130 rows x pitch 72 floats   [0 .. 9360)
// W hi/lo interleaved uint2 region:             [9360 .. 18064)
//   W1 seg: 32 kp x pitch 132 u2 = 4224 u2 (8448 floats)
//   W2:     64 kp x pitch  68 u2 = 4352 u2 (8704 floats)  <- region max
#define OFF_C   0
#define CPITCH  72
#define OFF_W   9360
#define SMEM_FLOATS 18064
#define SMEM_BYTES  (SMEM_FLOATS*4)   // 72256
#define W1P 132       // uint2 pitch, >=128 entries, ≡4 mod 16 -> conflict-free LDS.64
#define W2P 68        // uint2 pitch, >=64 entries,  ≡4 mod 16

__device__ float g_rw[4];
__device__ float g_alpha;
__device__ int   g_nev;
__device__ float g_buf0[(size_t)NTOK*D_MODEL];
__device__ float g_buf1[(size_t)NTOK*D_MODEL];

__device__ __forceinline__ float gelu_exact(float x){
    return 0.5f * x * (1.0f + erff(x * 0.7071067811865475f));
}
__device__ __forceinline__ void pack_hilo(float2 v, uint32_t& hi, uint32_t& lo){
    __nv_bfloat162 hb = __float22bfloat162_rn(v);
    float2 lv;
    lv.x = v.x - __bfloat162float(hb.x);
    lv.y = v.y - __bfloat162float(hb.y);
    __nv_bfloat162 lb = __float22bfloat162_rn(lv);
    hi = *(uint32_t*)&hb;
    lo = *(uint32_t*)&lb;
}
__device__ __forceinline__ void mma_bf16(float* d,
    uint32_t a0, uint32_t a1, uint32_t a2, uint32_t a3,
    uint32_t b0, uint32_t b1)
{
    asm volatile(
        "mma.sync.aligned.m16n8k16.row.col.f32.bf16.bf16.f32 "
        "{%0,%1,%2,%3},{%4,%5,%6,%7},{%8,%9},{%0,%1,%2,%3};"
        : "+f"(d[0]), "+f"(d[1]), "+f"(d[2]), "+f"(d[3])
        : "r"(a0), "r"(a1), "r"(a2), "r"(a3), "r"(b0), "r"(b1));
}

// ---------------- control kernel ----------------
__global__ void control_kernel(
    const float* __restrict__ c,
    const float* __restrict__ sw1, const float* __restrict__ sb1,
    const float* __restrict__ sw2, const float* __restrict__ sb2,
    const float* __restrict__ tw1, const float* __restrict__ tb1,
    const float* __restrict__ tw2, const float* __restrict__ tb2,
    const float* __restrict__ qw1, const float* __restrict__ qb1,
    const float* __restrict__ qw2, const float* __restrict__ qb2)
{
    __shared__ float cs[128], h1[64], h2[32], h3[32];
    int t = threadIdx.x;
    if (t < 128) cs[t] = c[t];
    __syncthreads();
    if (t < 64){
        float a = sb1[t];
        for (int k = 0; k < 128; k++) a += cs[k] * sw1[k*64 + t];
        h1[t] = gelu_exact(a);
    } else if (t < 96){
        int i = t - 64; float a = tb1[i];
        for (int k = 0; k < 128; k++) a += cs[k] * tw1[k*32 + i];
        h2[i] = gelu_exact(a);
    } else {
        int i = t - 96; float a = qb1[i];
        for (int k = 0; k < 128; k++) a += cs[k] * qw1[k*32 + i];
        h3[i] = gelu_exact(a);
    }
    __syncthreads();
    if (t == 0){
        float l[4], mx = -1e30f;
        for (int r = 0; r < 4; r++){
            float a = sb2[r];
            for (int i = 0; i < 64; i++) a += h1[i] * sw2[i*4 + r];
            l[r] = a; mx = fmaxf(mx, a);
        }
        float s = 0.f;
        for (int r = 0; r < 4; r++){ l[r] = expf(l[r]-mx); s += l[r]; }
        for (int r = 0; r < 4; r++) g_rw[r] = l[r]/s;
    }
    if (t == 1){
        float l[7], mx = -1e30f;
        for (int q = 0; q < 7; q++){
            float a = tb2[q];
            for (int i = 0; i < 32; i++) a += h2[i] * tw2[i*7 + q];
            l[q] = a; mx = fmaxf(mx, a);
        }
        float s = 0.f;
        for (int q = 0; q < 7; q++){ l[q] = expf(l[q]-mx); s += l[q]; }
        float nf = 0.f;
        for (int q = 0; q < 7; q++) nf += (l[q]/s) * (float)(q+2);
        int n = (int)(nf + 0.5f);
        g_nev = n < 2 ? 2 : (n > 8 ? 8 : n);
    }
    if (t == 2){
        float v = qb2[0];
        for (int i = 0; i < 32; i++) v += h3[i] * qw2[i];
        g_alpha = 0.1f + 0.8f / (1.0f + expf(-v));
    }
}

// ---------------- evolve step ----------------
__global__ void __launch_bounds__(NTHR, 1)
step_kernel(const float* __restrict__ cells_in,
            const float* __restrict__ rw1, const float* __restrict__ rb1,
            const float* __restrict__ rw2, const float* __restrict__ rb2,
            int j)
{
    if (j >= g_nev) return;

    extern __shared__ float sm[];
    float* cs = sm + OFF_C;
    uint2* ws = (uint2*)(sm + OFF_W);

    const float* src = (j == 0) ? cells_in : ((j & 1) ? g_buf0 : g_buf1);
    float*       dst = (j & 1) ? g_buf1 : g_buf0;

    const int tid  = threadIdx.x;
    const int w    = tid >> 5;
    const int lane = tid & 31;
    const int g    = lane >> 2;
    const int tig  = lane & 3;
    const int m0   = w * 16;

    const int brow = blockIdx.x >> 6;
    const int t0   = (blockIdx.x & 63) << 7;
    const float* rowbase = src + (size_t)brow * TT * D_MODEL;

    // load halo'd cells (fp32): rows t0-1 .. t0+128, pitch 72
    for (int i = tid; i < 130*16; i += NTHR){
        int row = i >> 4, c4 = i & 15;
        int t = (t0 - 1 + row) & (TT - 1);
        ((float4*)cs)[row*(CPITCH/4) + c4] =
            ((const float4*)(rowbase + (size_t)t * D_MODEL))[c4];
    }
    __syncthreads();

    float outa[32];
    #pragma unroll
    for (int i = 0; i < 32; i++) outa[i] = 0.0f;

    for (int r = 0; r < NRULES; r++){
        // ========== GEMM1: C1[128x128] = X3[128x192] @ W1 (3-term bf16) ==========
        float acc[16][4];
        #pragma unroll
        for (int a = 0; a < 16; a++){
            acc[a][0] = 0.f; acc[a][1] = 0.f; acc[a][2] = 0.f; acc[a][3] = 0.f;
        }

        for (int seg = 0; seg < 3; seg++){
            // stage W1 segment [64k x 128n] as interleaved (hi,lo) uint2
            {
                const float* w1g = rw1 + (size_t)r * K1 * HID + (size_t)seg * 64 * HID;
                #pragma unroll
                for (int it = 0; it < 16; it++){
                    int e  = it*NTHR + tid;       // 0..4095
                    int kp = e >> 7, n = e & 127;
                    float2 v;
                    v.x = __ldg(w1g + (size_t)(2*kp)   * HID + n);
                    v.y = __ldg(w1g + (size_t)(2*kp+1) * HID + n);
                    uint32_t hi, lo;
                    pack_hilo(v, hi, lo);
                    ws[kp*W1P + n] = make_uint2(hi, lo);
                }
            }
            __syncthreads();

            const int soff = (seg == 0) ? 1 : ((seg == 1) ? 0 : 2);
            const float* ra = cs + (size_t)(m0 + soff + g) * CPITCH;
            const float* rb = cs + (size_t)(m0 + soff + g + 8) * CPITCH;

            #pragma unroll
            for (int kt = 0; kt < 4; kt++){
                int kc = kt*16 + 2*tig;
                uint32_t ah0,ah1,ah2,ah3, al0,al1,al2,al3;
                pack_hilo(*(const float2*)(ra + kc),     ah0, al0);
                pack_hilo(*(const float2*)(rb + kc),     ah1, al1);
                pack_hilo(*(const float2*)(ra + kc + 8), ah2, al2);
                pack_hilo(*(const float2*)(rb + kc + 8), ah3, al3);
                const int kr0 = (kt*8 + tig)*W1P;
                const int kr1 = (kt*8 + tig + 4)*W1P;
                #pragma unroll
                for (int nt = 0; nt < 16; nt++){
                    int nc = nt*8 + g;
                    uint2 p0 = ws[kr0 + nc];
                    uint2 p1 = ws[kr1 + nc];
                    mma_bf16(acc[nt], ah0,ah1,ah2,ah3, p0.x, p1.x);
                    mma_bf16(acc[nt], al0,al1,al2,al3, p0.x, p1.x);
                    mma_bf16(acc[nt], ah0,ah1,ah2,ah3, p0.y, p1.y);
                }
            }
            __syncthreads();   // before next segment staging overwrites W buf
        }

        // ===== epilogue1 IN REGISTERS: h = gelu(C1 + b1), packed directly =====
        // into GEMM2 A fragments (C layout == A layout for same thread).
        uint32_t fh[8][4], fl[8][4];
        #pragma unroll
        for (int kt = 0; kt < 8; kt++){
            #pragma unroll
            for (int half = 0; half < 2; half++){
                int nt = 2*kt + half;
                int c  = nt*8 + 2*tig;
                const float2 b = __ldg((const float2*)(rb1 + r*HID + c));
                float2 va, vb;
                va.x = gelu_exact(acc[nt][0] + b.x);
                va.y = gelu_exact(acc[nt][1] + b.y);
                vb.x = gelu_exact(acc[nt][2] + b.x);
                vb.y = gelu_exact(acc[nt][3] + b.y);
                pack_hilo(va, fh[kt][half*2],   fl[kt][half*2]);
                pack_hilo(vb, fh[kt][half*2+1], fl[kt][half*2+1]);
            }
        }

        // stage W2 [128k x 64n] interleaved (hi,lo), pitch 68 u2
        {
            const float* w2g = rw2 + (size_t)r * HID * D_MODEL;
            #pragma unroll
            for (int it = 0; it < 16; it++){
                int e  = it*NTHR + tid;          // 0..4095
                int kp = e >> 6, n = e & 63;
                float2 v;
                v.x = __ldg(w2g + (size_t)(2*kp)   * D_MODEL + n);
                v.y = __ldg(w2g + (size_t)(2*kp+1) * D_MODEL + n);
                uint32_t hi, lo;
                pack_hilo(v, hi, lo);
                ws[kp*W2P + n] = make_uint2(hi, lo);
            }
        }
        __syncthreads();

        // ========== GEMM2: C2[128x64] = h @ W2 (A from registers) ==========
        float acc2[8][4];
        #pragma unroll
        for (int a = 0; a < 8; a++){
            acc2[a][0] = 0.f; acc2[a][1] = 0.f; acc2[a][2] = 0.f; acc2[a][3] = 0.f;
        }
        #pragma unroll
        for (int kt = 0; kt < 8; kt++){
            const int kr0 = (kt*8 + tig)*W2P;
            const int kr1 = (kt*8 + tig + 4)*W2P;
            #pragma unroll
            for (int nt = 0; nt < 8; nt++){
                int nc = nt*8 + g;
                uint2 p0 = ws[kr0 + nc];
                uint2 p1 = ws[kr1 + nc];
                mma_bf16(acc2[nt], fh[kt][0],fh[kt][1],fh[kt][2],fh[kt][3], p0.x, p1.x);
                mma_bf16(acc2[nt], fl[kt][0],fl[kt][1],fl[kt][2],fl[kt][3], p0.x, p1.x);
                mma_bf16(acc2[nt], fh[kt][0],fh[kt][1],fh[kt][2],fh[kt][3], p0.y, p1.y);
            }
        }

        // epilogue2: outa += rw[r] * tanh(C2 + b2)
        {
            const float rr = g_rw[r];
            #pragma unroll
            for (int nt = 0; nt < 8; nt++){
                int c = nt*8 + 2*tig;
                const float2 b = __ldg((const float2*)(rb2 + r*D_MODEL + c));
                outa[nt*4+0] += rr * tanhf(acc2[nt][0] + b.x);
                outa[nt*4+1] += rr * tanhf(acc2[nt][1] + b.y);
                outa[nt*4+2] += rr * tanhf(acc2[nt][2] + b.x);
                outa[nt*4+3] += rr * tanhf(acc2[nt][3] + b.y);
            }
        }
        __syncthreads();   // W buffer reused next rule
    }

    // residual mix + store: rows m0+g and m0+g+8
    {
        const float al = g_alpha, om = 1.0f - al;
        const float* cra = cs + (size_t)(m0 + 1 + g) * CPITCH;
        const float* crb = cs + (size_t)(m0 + 1 + g + 8) * CPITCH;
        float* da = dst + ((size_t)brow*TT + t0 + m0 + g) * D_MODEL;
        float* db = dst + ((size_t)brow*TT + t0 + m0 + g + 8) * D_MODEL;
        #pragma unroll
        for (int nt = 0; nt < 8; nt++){
            int c = nt*8 + 2*tig;
            float2 cva = *(const float2*)(cra + c);
            float2 cvb = *(const float2*)(crb + c);
            float2 oa, ob;
            oa.x = al*cva.x + om*outa[nt*4+0];
            oa.y = al*cva.y + om*outa[nt*4+1];
            ob.x = al*cvb.x + om*outa[nt*4+2];
            ob.y = al*cvb.y + om*outa[nt*4+3];
            *(float2*)(da + c) = oa;
            *(float2*)(db + c) = ob;
        }
    }
}

// ---------------- final LayerNorm ----------------
__global__ void __launch_bounds__(256)
ln_kernel(const float* __restrict__ g, const float* __restrict__ b,
          float* __restrict__ out)
{
    const float* src = ((g_nev - 1) & 1) ? g_buf1 : g_buf0;
    int tok  = blockIdx.x * 8 + (threadIdx.x >> 5);
    int lane = threadIdx.x & 31;
    float2 v = ((const float2*)(src + (size_t)tok * D_MODEL))[lane];
    float s = v.x + v.y;
    #pragma unroll
    for (int o = 16; o; o >>= 1) s += __shfl_xor_sync(0xffffffffu, s, o);
    float mu = s * (1.0f/64.0f);
    float dx = v.x - mu, dy = v.y - mu;
    float ss = dx*dx + dy*dy;
    #pragma unroll
    for (int o = 16; o; o >>= 1) ss += __shfl_xor_sync(0xffffffffu, ss, o);
    float rstd = rsqrtf(ss * (1.0f/64.0f) + LN_EPS);
    float2 gg = ((const float2*)g)[lane];
    float2 bb = ((const float2*)b)[lane];
    float2 ov;
    ov.x = dx * rstd * gg.x + bb.x;
    ov.y = dy * rstd * gg.y + bb.y;
    ((float2*)(out + (size_t)tok * D_MODEL))[lane] = ov;
}

// ---------------- launch ----------------
extern "C" void kernel_launch(void* const* d_in, const int* in_sizes, int n_in,
                              void* d_out, int out_size)
{
    const float* cells = (const float*)d_in[0];
    cudaFuncSetAttribute(step_kernel,
                         cudaFuncAttributeMaxDynamicSharedMemorySize, SMEM_BYTES);
    control_kernel<<<1, 128>>>((const float*)d_in[1],
        (const float*)d_in[6],  (const float*)d_in[7],
        (const float*)d_in[8],  (const float*)d_in[9],
        (const float*)d_in[10], (const float*)d_in[11],
        (const float*)d_in[12], (const float*)d_in[13],
        (const float*)d_in[14], (const float*)d_in[15],
        (const float*)d_in[16], (const float*)d_in[17]);
    for (int j = 0; j < 8; j++)
        step_kernel<<<NBLK, NTHR, SMEM_BYTES>>>(cells,
            (const float*)d_in[2], (const float*)d_in[3],
            (const float*)d_in[4], (const float*)d_in[5], j);
    ln_kernel<<<NTOK/8, 256>>>((const float*)d_in[18], (const float*)d_in[19],
                               (float*)d_out);
}